// round 16
// baseline (speedup 1.0000x reference)
#include <cuda_runtime.h>
#include <cuda_bf16.h>
#include <math.h>
#include <stdint.h>

// ---------------- static device scratch ----------------
__device__ __nv_bfloat16 g_col[(size_t)6400 * 4608];   // im2col bf16, 59 MB
__device__ __nv_bfloat16 g_wb[(size_t)544 * 4608];     // packed weights bf16
__device__ float g_a[256 * 800];                        // post BN+sigmoid
__device__ float g_pose[(size_t)6400 * 512];            // post BN
__device__ float g_wt[10 * 16 * 800];                   // W planar [c][d][i]

#define LN2PI_F 1.8378770664093453f
#define BN_EPS_F 1e-5f
#define EPS_F 1e-12f

__device__ __forceinline__ uint32_t smem_u32(const void* p) {
    uint32_t a;
    asm("{ .reg .u64 t; cvta.to.shared.u64 t, %1; cvt.u32.u64 %0, t; }"
        : "=r"(a) : "l"(p));
    return a;
}
__device__ __forceinline__ void cp_async16(uint32_t dst, const void* src) {
    asm volatile("cp.async.cg.shared.global [%0], [%1], 16;"
                 :: "r"(dst), "l"(src) : "memory");
}
#define CP_COMMIT() asm volatile("cp.async.commit_group;" ::: "memory")
#define CP_WAIT0()  asm volatile("cp.async.wait_group 0;" ::: "memory")

__device__ __forceinline__ void mma_bf16(
    float& c0, float& c1, float& c2, float& c3,
    uint32_t a0, uint32_t a1, uint32_t a2, uint32_t a3,
    uint32_t b0, uint32_t b1)
{
    asm volatile(
        "mma.sync.aligned.m16n8k16.row.col.f32.bf16.bf16.f32 "
        "{%0,%1,%2,%3}, {%4,%5,%6,%7}, {%8,%9}, {%0,%1,%2,%3};"
        : "+f"(c0), "+f"(c1), "+f"(c2), "+f"(c3)
        : "r"(a0), "r"(a1), "r"(a2), "r"(a3), "r"(b0), "r"(b1));
}
__device__ __forceinline__ void ldsm_x4(uint32_t& r0, uint32_t& r1,
                                        uint32_t& r2, uint32_t& r3, uint32_t a)
{
    asm volatile("ldmatrix.sync.aligned.m8n8.x4.shared.b16 {%0,%1,%2,%3}, [%4];"
                 : "=r"(r0), "=r"(r1), "=r"(r2), "=r"(r3) : "r"(a));
}
__device__ __forceinline__ void ldsm_x2(uint32_t& r0, uint32_t& r1, uint32_t a)
{
    asm volatile("ldmatrix.sync.aligned.m8n8.x2.shared.b16 {%0,%1}, [%2];"
                 : "=r"(r0), "=r"(r1) : "r"(a));
}

// ---------------- im2col: one CTA per batch, smem-staged ----------------
__global__ __launch_bounds__(512) void im2col_k(const float* __restrict__ x)
{
    extern __shared__ float xs[];            // [12800]
    int b = blockIdx.x;
    int tid = threadIdx.x;
    // coalesced stage of x[b] (12800 floats = 3200 float4)
    for (int idx = tid; idx < 3200; idx += 512)
        *(float4*)&xs[idx * 4] = *(const float4*)&x[(size_t)b * 12800 + idx * 4];
    __syncthreads();

    // 25 positions x 2304 bf16x2 pairs = 57600 pairs
    for (int u = tid; u < 57600; u += 512) {
        int p = u / 2304;
        int j = u - p * 2304;
        int y = p / 5, x0 = p - y * 5;
        int k0 = j * 2;
        float v[2];
#pragma unroll
        for (int t2 = 0; t2 < 2; t2++) {
            int k = k0 + t2;
            int ci = k / 9; int rem = k - ci * 9;
            int ky = rem / 3, kx = rem - ky * 3;
            int yy = y + ky - 1, xx = x0 + kx - 1;
            v[t2] = ((unsigned)yy < 5u && (unsigned)xx < 5u)
                        ? xs[ci * 25 + yy * 5 + xx] : 0.f;
        }
        __nv_bfloat162 o;
        o.x = __float2bfloat16(v[0]);
        o.y = __float2bfloat16(v[1]);
        *(__nv_bfloat162*)&g_col[(size_t)(b * 25 + p) * 4608 + k0] = o;
    }
}

// ---------------- weight pack: [544][4608] bf16 — R14-identical ------------
__global__ void wpack_k(const float* __restrict__ wa, const float* __restrict__ wp)
{
    int idx = blockIdx.x * 256 + threadIdx.x;
    if (idx >= 544 * 4608 / 4) return;
    int e = idx * 4;
    int n = e / 4608, k = e - n * 4608;
    const float* src = (n < 32) ? (wa + (size_t)n * 4608 + k)
                                : (wp + (size_t)(n - 32) * 4608 + k);
    float4 v = *(const float4*)src;
    __nv_bfloat162 o0, o1;
    o0.x = __float2bfloat16(v.x); o0.y = __float2bfloat16(v.y);
    o1.x = __float2bfloat16(v.z); o1.y = __float2bfloat16(v.w);
    *(__nv_bfloat162*)&g_wb[(size_t)n * 4608 + k]     = o0;
    *(__nv_bfloat162*)&g_wb[(size_t)n * 4608 + k + 2] = o1;
}

// ---------------- W transpose: [i][c][16] -> [c][d][i] — R14-identical -----
__global__ void wtrans_k(const float* __restrict__ Wg)
{
    int t = blockIdx.x * 256 + threadIdx.x;
    if (t >= 128000) return;
    int i = t % 800;
    int cd = t / 800;
    int c = cd >> 4, d = cd & 15;
    g_wt[t] = Wg[((size_t)i * 10 + c) * 16 + d];
}

// ---------------- bf16 mma.sync GEMM — R14-identical -----------------------
#define BK 64
#define TSTRIDE 72
#define ASTG (128 * TSTRIDE)
#define BSTG (64 * TSTRIDE)
#define NCHUNK 72

__global__ __launch_bounds__(256, 4) void gemm_bf16(
    const float* __restrict__ bag, const float* __restrict__ bab,
    const float* __restrict__ bam, const float* __restrict__ bav,
    const float* __restrict__ bpg, const float* __restrict__ bpb,
    const float* __restrict__ bpm, const float* __restrict__ bpv)
{
    extern __shared__ __nv_bfloat16 sm[];
    uint32_t sb = smem_u32(sm);

    int tid = threadIdx.x;
    int warp = tid >> 5, lane = tid & 31;
    int g = lane >> 2, q = lane & 3;
    int wm = warp & 3, wn = warp >> 2;

    int n0 = blockIdx.x * 64;
    int m0 = blockIdx.y * 128;

    float acc[2][4][4];
#pragma unroll
    for (int mt = 0; mt < 2; mt++)
#pragma unroll
        for (int nt = 0; nt < 4; nt++)
#pragma unroll
            for (int e = 0; e < 4; e++) acc[mt][nt][e] = 0.f;

    int arow[4], aq[4];
#pragma unroll
    for (int i = 0; i < 4; i++) {
        int u = i * 256 + tid;
        arow[i] = u >> 3; aq[i] = u & 7;
    }
    int brow[2], bq[2];
    bool bval[2];
#pragma unroll
    for (int i = 0; i < 2; i++) {
        int u = i * 256 + tid;
        brow[i] = u >> 3; bq[i] = u & 7;
        bval[i] = (n0 + brow[i]) < 544;
    }

    uint32_t lA[2];
#pragma unroll
    for (int mt = 0; mt < 2; mt++) {
        int row = wm * 32 + mt * 16 + (lane & 15);
        int col = (lane >> 4) * 8;
        lA[mt] = (uint32_t)(row * TSTRIDE + col) * 2;
    }
    uint32_t lB[4];
#pragma unroll
    for (int nt = 0; nt < 4; nt++) {
        int row = wn * 32 + nt * 8 + (lane & 7);
        int col = ((lane >> 3) & 1) * 8;
        lB[nt] = (uint32_t)(row * TSTRIDE + col) * 2;
    }

    auto load_chunk = [&](int s, int k0) {
        uint32_t abase = sb + (uint32_t)(s * ASTG) * 2;
        uint32_t bbase = sb + (uint32_t)(2 * ASTG + s * BSTG) * 2;
#pragma unroll
        for (int i = 0; i < 4; i++) {
            cp_async16(abase + arow[i] * (TSTRIDE * 2) + aq[i] * 16,
                       &g_col[(size_t)(m0 + arow[i]) * 4608 + k0 + aq[i] * 8]);
        }
#pragma unroll
        for (int i = 0; i < 2; i++) {
            uint32_t dst = bbase + brow[i] * (TSTRIDE * 2) + bq[i] * 16;
            if (bval[i]) {
                cp_async16(dst,
                           &g_wb[(size_t)(n0 + brow[i]) * 4608 + k0 + bq[i] * 8]);
            } else {
                *(uint4*)(((char*)sm) + (dst - sb)) = make_uint4(0, 0, 0, 0);
            }
        }
        CP_COMMIT();
    };

    load_chunk(0, 0);
    CP_WAIT0();
    __syncthreads();

    for (int c = 0; c < NCHUNK; c++) {
        int s = c & 1;
        if (c + 1 < NCHUNK) load_chunk(s ^ 1, (c + 1) * BK);

        uint32_t aSt = sb + (uint32_t)(s * ASTG) * 2;
        uint32_t bSt = sb + (uint32_t)(2 * ASTG + s * BSTG) * 2;

#pragma unroll
        for (int ks = 0; ks < 4; ks++) {
            uint32_t af[2][4];
#pragma unroll
            for (int mt = 0; mt < 2; mt++)
                ldsm_x4(af[mt][0], af[mt][1], af[mt][2], af[mt][3],
                        aSt + lA[mt] + ks * 32);
#pragma unroll
            for (int nt = 0; nt < 4; nt++) {
                uint32_t b0, b1;
                ldsm_x2(b0, b1, bSt + lB[nt] + ks * 32);
#pragma unroll
                for (int mt = 0; mt < 2; mt++)
                    mma_bf16(acc[mt][nt][0], acc[mt][nt][1],
                             acc[mt][nt][2], acc[mt][nt][3],
                             af[mt][0], af[mt][1], af[mt][2], af[mt][3],
                             b0, b1);
            }
        }
        CP_WAIT0();
        __syncthreads();
    }

#pragma unroll
    for (int mt = 0; mt < 2; mt++) {
#pragma unroll
        for (int nt = 0; nt < 4; nt++) {
#pragma unroll
            for (int e = 0; e < 4; e++) {
                int m = m0 + wm * 32 + mt * 16 + g + ((e >= 2) ? 8 : 0);
                int n = n0 + wn * 32 + nt * 8 + 2 * q + (e & 1);
                if (n >= 544) continue;
                int b = m / 25, p = m - b * 25;
                float val = acc[mt][nt][e];
                if (n < 32) {
                    float sc = bag[n] * rsqrtf(bav[n] + BN_EPS_F);
                    val = (val - bam[n]) * sc + bab[n];
                    g_a[b * 800 + p * 32 + n] = 1.f / (1.f + expf(-val));
                } else {
                    int co = n - 32;
                    float sc = bpg[co] * rsqrtf(bpv[co] + BN_EPS_F);
                    val = (val - bpm[co]) * sc + bpb[co];
                    g_pose[(size_t)m * 512 + co] = val;
                }
            }
        }
    }
}

// ---------------- EM routing — R14-identical --------------------------------
__global__ __launch_bounds__(320, 2) void routing_k(
    const float* __restrict__ beta_u, const float* __restrict__ beta_a,
    float* __restrict__ out)
{
    extern __shared__ float smf[];
    float* pose_r = smf;            // [800][16]
    float* r_sm   = smf + 12800;    // [10][800]  (holds r*au)
    float* au_sm  = r_sm + 8000;    // [800]
    float* part   = au_sm + 800;    // [10][33]
    float* mu_sm  = part + 330;     // [10][16]
    float* i2s_sm = mu_sm + 160;    // [10][16]
    float* ccst   = i2s_sm + 160;   // [10]
    float* aout   = ccst + 10;      // [10]

    int b = blockIdx.x;
    int tid = threadIdx.x;
    int c = tid >> 5;
    int lane = tid & 31;

    for (int idx = tid * 4; idx < 12800; idx += 320 * 4) {
        int i = idx >> 4, d = idx & 15;
        float4 v = *(const float4*)&g_pose[(size_t)(b * 25 + (i >> 5)) * 512 + (i & 31) * 16 + d];
        *(float4*)&pose_r[idx] = v;
    }
    for (int i = tid; i < 800; i += 320) au_sm[i] = g_a[b * 800 + i];
    __syncthreads();
    for (int idx = tid; idx < 8000; idx += 320)
        r_sm[idx] = au_sm[idx - (idx / 800) * 800];
    __syncthreads();

    const float lam_tab[3] = {0.0005f, 0.000975f, 0.00142625f};
    const float* Wc = g_wt + c * 16 * 800;

    for (int iter = 0; iter < 3; iter++) {
        float T0 = 0.f, T1[16], T2[16];
#pragma unroll
        for (int d = 0; d < 16; d++) { T1[d] = 0.f; T2[d] = 0.f; }

        const float* rrow = r_sm + c * 800;

#pragma unroll 1
        for (int k = 0; k < 25; k++) {
            int i = k * 32 + lane;
            float rw = rrow[i];
            float w[16];
#pragma unroll
            for (int d = 0; d < 16; d++)
                w[d] = __ldg(&Wc[d * 800 + i]);
            const float4* pp = (const float4*)(pose_r + i * 16);
            float4 p0 = pp[0], p1 = pp[1], p2 = pp[2], p3 = pp[3];
            float mr[16] = {p0.x, p0.y, p0.z, p0.w, p1.x, p1.y, p1.z, p1.w,
                            p2.x, p2.y, p2.z, p2.w, p3.x, p3.y, p3.z, p3.w};
            T0 += rw;
#pragma unroll
            for (int rr = 0; rr < 4; rr++) {
#pragma unroll
                for (int s = 0; s < 4; s++) {
                    float v = mr[rr * 4 + 0] * w[0 * 4 + s]
                            + mr[rr * 4 + 1] * w[1 * 4 + s]
                            + mr[rr * 4 + 2] * w[2 * 4 + s]
                            + mr[rr * 4 + 3] * w[3 * 4 + s];
                    T1[rr * 4 + s] += rw * v;
                    T2[rr * 4 + s] += rw * v * v;
                }
            }
        }

#pragma unroll
        for (int o = 16; o; o >>= 1) {
            T0 += __shfl_xor_sync(0xffffffffu, T0, o);
#pragma unroll
            for (int d = 0; d < 16; d++) {
                T1[d] += __shfl_xor_sync(0xffffffffu, T1[d], o);
                T2[d] += __shfl_xor_sync(0xffffffffu, T2[d], o);
            }
        }
        if (lane == 0) {
            float* pp = part + c * 33;
            pp[0] = T0;
#pragma unroll
            for (int d = 0; d < 16; d++) { pp[1 + d] = T1[d]; pp[17 + d] = T2[d]; }
        }
        __syncthreads();

        if (tid < 10) {
            int cc = tid;
            const float* pa = part + cc * 33;
            float t0 = pa[0];
            float dn = 1.f / (t0 + EPS_F);
            float t = dn * t0;
            float bu = beta_u[cc];
            float cost = 0.f, lnp = 0.f;
#pragma unroll
            for (int d = 0; d < 16; d++) {
                float mu = dn * pa[1 + d];
                float sig = fmaxf(dn * pa[17 + d] - mu * mu * (2.f - t), 0.f) + EPS_F;
                mu_sm[cc * 16 + d] = mu;
                i2s_sm[cc * 16 + d] = 0.5f / sig;
                float lg = logf(sig);
                cost += bu + 0.5f * lg;
                lnp += -0.5f * logf(sig * LN2PI_F);
            }
            float lam = lam_tab[iter];
            float ao = 1.f / (1.f + expf(-lam * (beta_a[cc] - cost * t0)));
            aout[cc] = ao;
            ccst[cc] = lnp + logf(ao);
        }
        __syncthreads();

        if (iter < 2) {
            for (int i = tid; i < 800; i += 320) {
                const float4* pp = (const float4*)(pose_r + i * 16);
                float4 p0 = pp[0], p1 = pp[1], p2 = pp[2], p3 = pp[3];
                float mr[16] = {p0.x, p0.y, p0.z, p0.w, p1.x, p1.y, p1.z, p1.w,
                                p2.x, p2.y, p2.z, p2.w, p3.x, p3.y, p3.z, p3.w};
                float lp[10];
                float mx = -1e30f;
#pragma unroll
                for (int cc = 0; cc < 10; cc++) {
                    const float* Wp = g_wt + cc * 16 * 800 + i;
                    float w[16];
#pragma unroll
                    for (int d = 0; d < 16; d++)
                        w[d] = __ldg(&Wp[d * 800]);
                    float s = 0.f;
#pragma unroll
                    for (int rr = 0; rr < 4; rr++) {
#pragma unroll
                        for (int ss = 0; ss < 4; ss++) {
                            float v = mr[rr * 4 + 0] * w[ss]
                                    + mr[rr * 4 + 1] * w[4 + ss]
                                    + mr[rr * 4 + 2] * w[8 + ss]
                                    + mr[rr * 4 + 3] * w[12 + ss];
                            float dv = v - mu_sm[cc * 16 + rr * 4 + ss];
                            s += dv * dv * i2s_sm[cc * 16 + rr * 4 + ss];
                        }
                    }
                    lp[cc] = ccst[cc] - s;
                    mx = fmaxf(mx, lp[cc]);
                }
                float sum = 0.f;
#pragma unroll
                for (int cc = 0; cc < 10; cc++) { lp[cc] = expf(lp[cc] - mx); sum += lp[cc]; }
                float inv = au_sm[i] / sum;
#pragma unroll
                for (int cc = 0; cc < 10; cc++) r_sm[cc * 800 + i] = lp[cc] * inv;
            }
            __syncthreads();
        }
    }

    if (tid == 0) {
        float s = 0.f;
#pragma unroll
        for (int cc = 0; cc < 10; cc++) s += aout[cc];
        float ls = logf(s);
#pragma unroll
        for (int cc = 0; cc < 10; cc++)
            out[b * 10 + cc] = logf(aout[cc]) - ls;
    }
}

// ---------------- launcher ----------------
extern "C" void kernel_launch(void* const* d_in, const int* in_sizes, int n_in,
                              void* d_out, int out_size)
{
    const float* x      = (const float*)d_in[0];
    const float* w_a    = (const float*)d_in[1];
    const float* w_pose = (const float*)d_in[2];
    const float* bn_a_g = (const float*)d_in[3];
    const float* bn_a_b = (const float*)d_in[4];
    const float* bn_a_m = (const float*)d_in[5];
    const float* bn_a_v = (const float*)d_in[6];
    const float* bn_p_g = (const float*)d_in[7];
    const float* bn_p_b = (const float*)d_in[8];
    const float* bn_p_m = (const float*)d_in[9];
    const float* bn_p_v = (const float*)d_in[10];
    const float* W      = (const float*)d_in[11];
    const float* beta_u = (const float*)d_in[12];
    const float* beta_a = (const float*)d_in[13];
    float* out = (float*)d_out;

    const int gemm_smem = (2 * ASTG + 2 * BSTG) * (int)sizeof(__nv_bfloat16); // 55296
    const int rout_smem = (12800 + 8000 + 800 + 330 + 160 + 160 + 10 + 10 + 14) * 4;
    const int i2c_smem  = 12800 * 4;
    cudaFuncSetAttribute(gemm_bf16, cudaFuncAttributeMaxDynamicSharedMemorySize,
                         gemm_smem);
    cudaFuncSetAttribute(routing_k, cudaFuncAttributeMaxDynamicSharedMemorySize,
                         rout_smem);
    cudaFuncSetAttribute(im2col_k, cudaFuncAttributeMaxDynamicSharedMemorySize,
                         i2c_smem);

    im2col_k<<<256, 512, i2c_smem>>>(x);

    wpack_k<<<(544 * 4608 / 4 + 255) / 256, 256>>>(w_a, w_pose);
    wtrans_k<<<(128000 + 255) / 256, 256>>>(W);

    dim3 gg(9, 50);
    gemm_bf16<<<gg, 256, gemm_smem>>>(bn_a_g, bn_a_b, bn_a_m, bn_a_v,
                                      bn_p_g, bn_p_b, bn_p_m, bn_p_v);

    routing_k<<<256, 320, rout_smem>>>(beta_u, beta_a, out);
}

// round 17
// speedup vs baseline: 1.0873x; 1.0873x over previous
#include <cuda_runtime.h>
#include <cuda_bf16.h>
#include <math.h>
#include <stdint.h>

// ---------------- static device scratch ----------------
__device__ __nv_bfloat16 g_col[(size_t)6400 * 4608];   // im2col bf16, 59 MB
__device__ __nv_bfloat16 g_wb[(size_t)544 * 4608];     // packed weights bf16
__device__ float g_a[256 * 800];                        // post BN+sigmoid
__device__ float g_pose[(size_t)6400 * 512];            // post BN
__device__ float g_wt[10 * 16 * 800];                   // W planar [c][d][i]

#define LN2PI_F 1.8378770664093453f
#define BN_EPS_F 1e-5f
#define EPS_F 1e-12f

__device__ __forceinline__ uint32_t smem_u32(const void* p) {
    uint32_t a;
    asm("{ .reg .u64 t; cvta.to.shared.u64 t, %1; cvt.u32.u64 %0, t; }"
        : "=r"(a) : "l"(p));
    return a;
}
__device__ __forceinline__ void cp_async16(uint32_t dst, const void* src) {
    asm volatile("cp.async.cg.shared.global [%0], [%1], 16;"
                 :: "r"(dst), "l"(src) : "memory");
}
#define CP_COMMIT() asm volatile("cp.async.commit_group;" ::: "memory")
#define CP_WAIT0()  asm volatile("cp.async.wait_group 0;" ::: "memory")

__device__ __forceinline__ void mma_bf16(
    float& c0, float& c1, float& c2, float& c3,
    uint32_t a0, uint32_t a1, uint32_t a2, uint32_t a3,
    uint32_t b0, uint32_t b1)
{
    asm volatile(
        "mma.sync.aligned.m16n8k16.row.col.f32.bf16.bf16.f32 "
        "{%0,%1,%2,%3}, {%4,%5,%6,%7}, {%8,%9}, {%0,%1,%2,%3};"
        : "+f"(c0), "+f"(c1), "+f"(c2), "+f"(c3)
        : "r"(a0), "r"(a1), "r"(a2), "r"(a3), "r"(b0), "r"(b1));
}
__device__ __forceinline__ void ldsm_x4(uint32_t& r0, uint32_t& r1,
                                        uint32_t& r2, uint32_t& r3, uint32_t a)
{
    asm volatile("ldmatrix.sync.aligned.m8n8.x4.shared.b16 {%0,%1,%2,%3}, [%4];"
                 : "=r"(r0), "=r"(r1), "=r"(r2), "=r"(r3) : "r"(a));
}
__device__ __forceinline__ void ldsm_x2(uint32_t& r0, uint32_t& r1, uint32_t a)
{
    asm volatile("ldmatrix.sync.aligned.m8n8.x2.shared.b16 {%0,%1}, [%2];"
                 : "=r"(r0), "=r"(r1) : "r"(a));
}

// ---------------- im2col: 6400 CTAs, 9 coalesced chunks per thread (R14) ---
__global__ __launch_bounds__(256) void im2col_k(const float* __restrict__ x)
{
    int m = blockIdx.x;
    int b = m / 25, p = m - b * 25;
    int y = p / 5, x0 = p - y * 5;
    int tid = threadIdx.x;
#pragma unroll
    for (int j = 0; j < 9; j++) {
        int k0 = j * 512 + tid * 2;
        float v[2];
#pragma unroll
        for (int t2 = 0; t2 < 2; t2++) {
            int k = k0 + t2;
            int ci = k / 9; int rem = k - ci * 9;
            int ky = rem / 3, kx = rem - ky * 3;
            int yy = y + ky - 1, xx = x0 + kx - 1;
            v[t2] = 0.f;
            if ((unsigned)yy < 5u && (unsigned)xx < 5u)
                v[t2] = x[((b * 512 + ci) * 5 + yy) * 5 + xx];
        }
        __nv_bfloat162 o;
        o.x = __float2bfloat16(v[0]);
        o.y = __float2bfloat16(v[1]);
        *(__nv_bfloat162*)&g_col[(size_t)m * 4608 + k0] = o;
    }
}

// -------- fused prep: weight pack (bf16) + W planar transpose --------------
// idx < 626688: wpack (4 elems each). idx in [626688, 754688): wtrans (1 elem).
__global__ void prep_k(const float* __restrict__ wa, const float* __restrict__ wp,
                       const float* __restrict__ Wg)
{
    int idx = blockIdx.x * 256 + threadIdx.x;
    if (idx < 544 * 4608 / 4) {
        int e = idx * 4;
        int n = e / 4608, k = e - n * 4608;
        const float* src = (n < 32) ? (wa + (size_t)n * 4608 + k)
                                    : (wp + (size_t)(n - 32) * 4608 + k);
        float4 v = *(const float4*)src;
        __nv_bfloat162 o0, o1;
        o0.x = __float2bfloat16(v.x); o0.y = __float2bfloat16(v.y);
        o1.x = __float2bfloat16(v.z); o1.y = __float2bfloat16(v.w);
        *(__nv_bfloat162*)&g_wb[(size_t)n * 4608 + k]     = o0;
        *(__nv_bfloat162*)&g_wb[(size_t)n * 4608 + k + 2] = o1;
    } else {
        int t = idx - 544 * 4608 / 4;
        if (t >= 128000) return;
        int i = t % 800;
        int cd = t / 800;
        int c = cd >> 4, d = cd & 15;
        g_wt[t] = Wg[((size_t)i * 10 + c) * 16 + d];
    }
}

// ---------------- bf16 mma.sync GEMM — R14-identical -----------------------
#define BK 64
#define TSTRIDE 72
#define ASTG (128 * TSTRIDE)
#define BSTG (64 * TSTRIDE)
#define NCHUNK 72

__global__ __launch_bounds__(256, 4) void gemm_bf16(
    const float* __restrict__ bag, const float* __restrict__ bab,
    const float* __restrict__ bam, const float* __restrict__ bav,
    const float* __restrict__ bpg, const float* __restrict__ bpb,
    const float* __restrict__ bpm, const float* __restrict__ bpv)
{
    extern __shared__ __nv_bfloat16 sm[];
    uint32_t sb = smem_u32(sm);

    int tid = threadIdx.x;
    int warp = tid >> 5, lane = tid & 31;
    int g = lane >> 2, q = lane & 3;
    int wm = warp & 3, wn = warp >> 2;

    int n0 = blockIdx.x * 64;
    int m0 = blockIdx.y * 128;

    float acc[2][4][4];
#pragma unroll
    for (int mt = 0; mt < 2; mt++)
#pragma unroll
        for (int nt = 0; nt < 4; nt++)
#pragma unroll
            for (int e = 0; e < 4; e++) acc[mt][nt][e] = 0.f;

    int arow[4], aq[4];
#pragma unroll
    for (int i = 0; i < 4; i++) {
        int u = i * 256 + tid;
        arow[i] = u >> 3; aq[i] = u & 7;
    }
    int brow[2], bq[2];
    bool bval[2];
#pragma unroll
    for (int i = 0; i < 2; i++) {
        int u = i * 256 + tid;
        brow[i] = u >> 3; bq[i] = u & 7;
        bval[i] = (n0 + brow[i]) < 544;
    }

    uint32_t lA[2];
#pragma unroll
    for (int mt = 0; mt < 2; mt++) {
        int row = wm * 32 + mt * 16 + (lane & 15);
        int col = (lane >> 4) * 8;
        lA[mt] = (uint32_t)(row * TSTRIDE + col) * 2;
    }
    uint32_t lB[4];
#pragma unroll
    for (int nt = 0; nt < 4; nt++) {
        int row = wn * 32 + nt * 8 + (lane & 7);
        int col = ((lane >> 3) & 1) * 8;
        lB[nt] = (uint32_t)(row * TSTRIDE + col) * 2;
    }

    auto load_chunk = [&](int s, int k0) {
        uint32_t abase = sb + (uint32_t)(s * ASTG) * 2;
        uint32_t bbase = sb + (uint32_t)(2 * ASTG + s * BSTG) * 2;
#pragma unroll
        for (int i = 0; i < 4; i++) {
            cp_async16(abase + arow[i] * (TSTRIDE * 2) + aq[i] * 16,
                       &g_col[(size_t)(m0 + arow[i]) * 4608 + k0 + aq[i] * 8]);
        }
#pragma unroll
        for (int i = 0; i < 2; i++) {
            uint32_t dst = bbase + brow[i] * (TSTRIDE * 2) + bq[i] * 16;
            if (bval[i]) {
                cp_async16(dst,
                           &g_wb[(size_t)(n0 + brow[i]) * 4608 + k0 + bq[i] * 8]);
            } else {
                *(uint4*)(((char*)sm) + (dst - sb)) = make_uint4(0, 0, 0, 0);
            }
        }
        CP_COMMIT();
    };

    load_chunk(0, 0);
    CP_WAIT0();
    __syncthreads();

    for (int c = 0; c < NCHUNK; c++) {
        int s = c & 1;
        if (c + 1 < NCHUNK) load_chunk(s ^ 1, (c + 1) * BK);

        uint32_t aSt = sb + (uint32_t)(s * ASTG) * 2;
        uint32_t bSt = sb + (uint32_t)(2 * ASTG + s * BSTG) * 2;

#pragma unroll
        for (int ks = 0; ks < 4; ks++) {
            uint32_t af[2][4];
#pragma unroll
            for (int mt = 0; mt < 2; mt++)
                ldsm_x4(af[mt][0], af[mt][1], af[mt][2], af[mt][3],
                        aSt + lA[mt] + ks * 32);
#pragma unroll
            for (int nt = 0; nt < 4; nt++) {
                uint32_t b0, b1;
                ldsm_x2(b0, b1, bSt + lB[nt] + ks * 32);
#pragma unroll
                for (int mt = 0; mt < 2; mt++)
                    mma_bf16(acc[mt][nt][0], acc[mt][nt][1],
                             acc[mt][nt][2], acc[mt][nt][3],
                             af[mt][0], af[mt][1], af[mt][2], af[mt][3],
                             b0, b1);
            }
        }
        CP_WAIT0();
        __syncthreads();
    }

#pragma unroll
    for (int mt = 0; mt < 2; mt++) {
#pragma unroll
        for (int nt = 0; nt < 4; nt++) {
#pragma unroll
            for (int e = 0; e < 4; e++) {
                int m = m0 + wm * 32 + mt * 16 + g + ((e >= 2) ? 8 : 0);
                int n = n0 + wn * 32 + nt * 8 + 2 * q + (e & 1);
                if (n >= 544) continue;
                int b = m / 25, p = m - b * 25;
                float val = acc[mt][nt][e];
                if (n < 32) {
                    float sc = bag[n] * rsqrtf(bav[n] + BN_EPS_F);
                    val = (val - bam[n]) * sc + bab[n];
                    g_a[b * 800 + p * 32 + n] = 1.f / (1.f + expf(-val));
                } else {
                    int co = n - 32;
                    float sc = bpg[co] * rsqrtf(bpv[co] + BN_EPS_F);
                    val = (val - bpm[co]) * sc + bpb[co];
                    g_pose[(size_t)m * 512 + co] = val;
                }
            }
        }
    }
}

// ---------------- EM routing — R14-identical --------------------------------
__global__ __launch_bounds__(320, 2) void routing_k(
    const float* __restrict__ beta_u, const float* __restrict__ beta_a,
    float* __restrict__ out)
{
    extern __shared__ float smf[];
    float* pose_r = smf;            // [800][16]
    float* r_sm   = smf + 12800;    // [10][800]  (holds r*au)
    float* au_sm  = r_sm + 8000;    // [800]
    float* part   = au_sm + 800;    // [10][33]
    float* mu_sm  = part + 330;     // [10][16]
    float* i2s_sm = mu_sm + 160;    // [10][16]
    float* ccst   = i2s_sm + 160;   // [10]
    float* aout   = ccst + 10;      // [10]

    int b = blockIdx.x;
    int tid = threadIdx.x;
    int c = tid >> 5;
    int lane = tid & 31;

    for (int idx = tid * 4; idx < 12800; idx += 320 * 4) {
        int i = idx >> 4, d = idx & 15;
        float4 v = *(const float4*)&g_pose[(size_t)(b * 25 + (i >> 5)) * 512 + (i & 31) * 16 + d];
        *(float4*)&pose_r[idx] = v;
    }
    for (int i = tid; i < 800; i += 320) au_sm[i] = g_a[b * 800 + i];
    __syncthreads();
    for (int idx = tid; idx < 8000; idx += 320)
        r_sm[idx] = au_sm[idx - (idx / 800) * 800];
    __syncthreads();

    const float lam_tab[3] = {0.0005f, 0.000975f, 0.00142625f};
    const float* Wc = g_wt + c * 16 * 800;

    for (int iter = 0; iter < 3; iter++) {
        float T0 = 0.f, T1[16], T2[16];
#pragma unroll
        for (int d = 0; d < 16; d++) { T1[d] = 0.f; T2[d] = 0.f; }

        const float* rrow = r_sm + c * 800;

#pragma unroll 1
        for (int k = 0; k < 25; k++) {
            int i = k * 32 + lane;
            float rw = rrow[i];
            float w[16];
#pragma unroll
            for (int d = 0; d < 16; d++)
                w[d] = __ldg(&Wc[d * 800 + i]);
            const float4* pp = (const float4*)(pose_r + i * 16);
            float4 p0 = pp[0], p1 = pp[1], p2 = pp[2], p3 = pp[3];
            float mr[16] = {p0.x, p0.y, p0.z, p0.w, p1.x, p1.y, p1.z, p1.w,
                            p2.x, p2.y, p2.z, p2.w, p3.x, p3.y, p3.z, p3.w};
            T0 += rw;
#pragma unroll
            for (int rr = 0; rr < 4; rr++) {
#pragma unroll
                for (int s = 0; s < 4; s++) {
                    float v = mr[rr * 4 + 0] * w[0 * 4 + s]
                            + mr[rr * 4 + 1] * w[1 * 4 + s]
                            + mr[rr * 4 + 2] * w[2 * 4 + s]
                            + mr[rr * 4 + 3] * w[3 * 4 + s];
                    T1[rr * 4 + s] += rw * v;
                    T2[rr * 4 + s] += rw * v * v;
                }
            }
        }

#pragma unroll
        for (int o = 16; o; o >>= 1) {
            T0 += __shfl_xor_sync(0xffffffffu, T0, o);
#pragma unroll
            for (int d = 0; d < 16; d++) {
                T1[d] += __shfl_xor_sync(0xffffffffu, T1[d], o);
                T2[d] += __shfl_xor_sync(0xffffffffu, T2[d], o);
            }
        }
        if (lane == 0) {
            float* pp = part + c * 33;
            pp[0] = T0;
#pragma unroll
            for (int d = 0; d < 16; d++) { pp[1 + d] = T1[d]; pp[17 + d] = T2[d]; }
        }
        __syncthreads();

        if (tid < 10) {
            int cc = tid;
            const float* pa = part + cc * 33;
            float t0 = pa[0];
            float dn = 1.f / (t0 + EPS_F);
            float t = dn * t0;
            float bu = beta_u[cc];
            float cost = 0.f, lnp = 0.f;
#pragma unroll
            for (int d = 0; d < 16; d++) {
                float mu = dn * pa[1 + d];
                float sig = fmaxf(dn * pa[17 + d] - mu * mu * (2.f - t), 0.f) + EPS_F;
                mu_sm[cc * 16 + d] = mu;
                i2s_sm[cc * 16 + d] = 0.5f / sig;
                float lg = logf(sig);
                cost += bu + 0.5f * lg;
                lnp += -0.5f * logf(sig * LN2PI_F);
            }
            float lam = lam_tab[iter];
            float ao = 1.f / (1.f + expf(-lam * (beta_a[cc] - cost * t0)));
            aout[cc] = ao;
            ccst[cc] = lnp + logf(ao);
        }
        __syncthreads();

        if (iter < 2) {
            for (int i = tid; i < 800; i += 320) {
                const float4* pp = (const float4*)(pose_r + i * 16);
                float4 p0 = pp[0], p1 = pp[1], p2 = pp[2], p3 = pp[3];
                float mr[16] = {p0.x, p0.y, p0.z, p0.w, p1.x, p1.y, p1.z, p1.w,
                                p2.x, p2.y, p2.z, p2.w, p3.x, p3.y, p3.z, p3.w};
                float lp[10];
                float mx = -1e30f;
#pragma unroll
                for (int cc = 0; cc < 10; cc++) {
                    const float* Wp = g_wt + cc * 16 * 800 + i;
                    float w[16];
#pragma unroll
                    for (int d = 0; d < 16; d++)
                        w[d] = __ldg(&Wp[d * 800]);
                    float s = 0.f;
#pragma unroll
                    for (int rr = 0; rr < 4; rr++) {
#pragma unroll
                        for (int ss = 0; ss < 4; ss++) {
                            float v = mr[rr * 4 + 0] * w[ss]
                                    + mr[rr * 4 + 1] * w[4 + ss]
                                    + mr[rr * 4 + 2] * w[8 + ss]
                                    + mr[rr * 4 + 3] * w[12 + ss];
                            float dv = v - mu_sm[cc * 16 + rr * 4 + ss];
                            s += dv * dv * i2s_sm[cc * 16 + rr * 4 + ss];
                        }
                    }
                    lp[cc] = ccst[cc] - s;
                    mx = fmaxf(mx, lp[cc]);
                }
                float sum = 0.f;
#pragma unroll
                for (int cc = 0; cc < 10; cc++) { lp[cc] = expf(lp[cc] - mx); sum += lp[cc]; }
                float inv = au_sm[i] / sum;
#pragma unroll
                for (int cc = 0; cc < 10; cc++) r_sm[cc * 800 + i] = lp[cc] * inv;
            }
            __syncthreads();
        }
    }

    if (tid == 0) {
        float s = 0.f;
#pragma unroll
        for (int cc = 0; cc < 10; cc++) s += aout[cc];
        float ls = logf(s);
#pragma unroll
        for (int cc = 0; cc < 10; cc++)
            out[b * 10 + cc] = logf(aout[cc]) - ls;
    }
}

// ---------------- launcher ----------------
extern "C" void kernel_launch(void* const* d_in, const int* in_sizes, int n_in,
                              void* d_out, int out_size)
{
    const float* x      = (const float*)d_in[0];
    const float* w_a    = (const float*)d_in[1];
    const float* w_pose = (const float*)d_in[2];
    const float* bn_a_g = (const float*)d_in[3];
    const float* bn_a_b = (const float*)d_in[4];
    const float* bn_a_m = (const float*)d_in[5];
    const float* bn_a_v = (const float*)d_in[6];
    const float* bn_p_g = (const float*)d_in[7];
    const float* bn_p_b = (const float*)d_in[8];
    const float* bn_p_m = (const float*)d_in[9];
    const float* bn_p_v = (const float*)d_in[10];
    const float* W      = (const float*)d_in[11];
    const float* beta_u = (const float*)d_in[12];
    const float* beta_a = (const float*)d_in[13];
    float* out = (float*)d_out;

    const int gemm_smem = (2 * ASTG + 2 * BSTG) * (int)sizeof(__nv_bfloat16); // 55296
    const int rout_smem = (12800 + 8000 + 800 + 330 + 160 + 160 + 10 + 10 + 14) * 4;
    cudaFuncSetAttribute(gemm_bf16, cudaFuncAttributeMaxDynamicSharedMemorySize,
                         gemm_smem);
    cudaFuncSetAttribute(routing_k, cudaFuncAttributeMaxDynamicSharedMemorySize,
                         rout_smem);

    // fused prep first (independent of im2col); one launch for both packs
    const int prep_items = 544 * 4608 / 4 + 128000;   // 626688 + 128000
    prep_k<<<(prep_items + 255) / 256, 256>>>(w_a, w_pose, W);

    im2col_k<<<6400, 256>>>(x);

    dim3 gg(9, 50);
    gemm_bf16<<<gg, 256, gemm_smem>>>(bn_a_g, bn_a_b, bn_a_m, bn_a_v,
                                      bn_p_g, bn_p_b, bn_p_m, bn_p_v);

    routing_k<<<256, 320, rout_smem>>>(beta_u, beta_a, out);
}